// round 17
// baseline (speedup 1.0000x reference)
#include <cuda_runtime.h>
#include <cuda_bf16.h>
#include <math_constants.h>
#include <cstdint>

// Problem constants
#define BATCH   2
#define SEQ     2048
#define CMODEL  1024
#define NHEADS  16
#define DHEAD   64
#define MROWS   (BATCH * SEQ)          // 4096
#define QKV_N   (3 * CMODEL)           // 3072

// Scratch (allocation-free rule: __device__ globals)
__device__ float g_qkv[(size_t)MROWS * QKV_N];    // [4096, 3072] Q|K|V (fp32)
__device__ float g_y[(size_t)MROWS * CMODEL];     // [4096, 1024] attn out (tf32-rounded)
__device__ float g_xc[(size_t)MROWS * CMODEL];    // x, tf32-rounded
__device__ float g_wqkvc[(size_t)CMODEL * QKV_N]; // w_qkv, tf32-rounded
__device__ float g_woutc[(size_t)CMODEL * CMODEL];// w_out, tf32-rounded

// ---------------------------------------------------------------------------
// Helpers
// ---------------------------------------------------------------------------
__device__ __forceinline__ uint32_t f2tf32(float x) {
    uint32_t u;
    asm("cvt.rna.tf32.f32 %0, %1;" : "=r"(u) : "f"(x));
    return u;
}
__device__ __forceinline__ float rtf(float x) {
    return __uint_as_float(f2tf32(x));
}

__device__ __forceinline__ void mma_tf32(float acc[4], const uint32_t a[4],
                                         const uint32_t b[2]) {
    asm("mma.sync.aligned.m16n8k8.row.col.f32.tf32.tf32.f32 "
        "{%0,%1,%2,%3}, {%4,%5,%6,%7}, {%8,%9}, {%0,%1,%2,%3};"
        : "+f"(acc[0]), "+f"(acc[1]), "+f"(acc[2]), "+f"(acc[3])
        : "r"(a[0]), "r"(a[1]), "r"(a[2]), "r"(a[3]), "r"(b[0]), "r"(b[1]));
}

__device__ __forceinline__ void mma_bf16(float acc[4], const uint32_t a[4],
                                         const uint32_t b0, const uint32_t b1) {
    asm("mma.sync.aligned.m16n8k16.row.col.f32.bf16.bf16.f32 "
        "{%0,%1,%2,%3}, {%4,%5,%6,%7}, {%8,%9}, {%0,%1,%2,%3};"
        : "+f"(acc[0]), "+f"(acc[1]), "+f"(acc[2]), "+f"(acc[3])
        : "r"(a[0]), "r"(a[1]), "r"(a[2]), "r"(a[3]), "r"(b0), "r"(b1));
}

// bf16 hi/lo split of two floats -> packed hi pair + packed lo pair.
__device__ __forceinline__ void split_pair_bf16(float e0, float e1,
                                                uint32_t& hi, uint32_t& lo) {
    uint16_t h0 = __bfloat16_as_ushort(__float2bfloat16_rn(e0));
    uint16_t h1 = __bfloat16_as_ushort(__float2bfloat16_rn(e1));
    hi = ((uint32_t)h1 << 16) | h0;
    float r0 = e0 - __uint_as_float((uint32_t)h0 << 16);
    float r1 = e1 - __uint_as_float((uint32_t)h1 << 16);
    uint16_t l0 = __bfloat16_as_ushort(__float2bfloat16_rn(r0));
    uint16_t l1 = __bfloat16_as_ushort(__float2bfloat16_rn(r1));
    lo = ((uint32_t)l1 << 16) | l0;
}

__device__ __forceinline__ void cp16(void* dst, const void* src) {
    uint32_t d = (uint32_t)__cvta_generic_to_shared(dst);
    asm volatile("cp.async.cg.shared.global [%0], [%1], 16;" :: "r"(d), "l"(src));
}
#define CP_COMMIT() asm volatile("cp.async.commit_group;")
#define CP_WAIT0()  asm volatile("cp.async.wait_group 0;")

// ---------------------------------------------------------------------------
// Elementwise tf32 rounding (pre-conversion). n divisible by 4.
// ---------------------------------------------------------------------------
__global__ void cvt_tf32_kernel(const float* __restrict__ in,
                                float* __restrict__ out, int n4)
{
    int i = blockIdx.x * blockDim.x + threadIdx.x;
    if (i < n4) {
        float4 v = ((const float4*)in)[i];
        float4 o;
        o.x = rtf(v.x); o.y = rtf(v.y); o.z = rtf(v.z); o.w = rtf(v.w);
        ((float4*)out)[i] = o;
    }
}

// ---------------------------------------------------------------------------
// TF32 GEMM v2, fused bias. Block tile 64x128, BK=16, 256 threads (8 warps,
// 2x4 grid), warp tile 32x32 -> acc 32 regs. __launch_bounds__(256,3) caps
// regs at 85 => 3 CTAs/SM (37.5% occ vs 22.5% before). Same per-output
// arithmetic order as v1 (BKK=16, two k8 steps) -> numerically identical.
// smem 27,648 B/CTA (regs bind occupancy, not smem).
// ---------------------------------------------------------------------------
#define BMM 64
#define BN 128
#define BKK 16
#define ALD 20
#define LDB 136

__global__ __launch_bounds__(256, 3)
void tf32_gemm_bias(const float* __restrict__ A,
                    const float* __restrict__ B,
                    const float* __restrict__ bias,
                    float* __restrict__ C,
                    int M, int N, int K)
{
    __shared__ float As[2][BMM][ALD];
    __shared__ float Bs[2][BKK][LDB];

    const int tid  = threadIdx.x;
    const int warp = tid >> 5;
    const int lane = tid & 31;
    const int gid  = lane >> 2;
    const int tig  = lane & 3;
    const int warpRow = (warp & 1) * 32;    // 2 warps in M (32 rows each)
    const int warpCol = (warp >> 1) * 32;   // 4 warps in N (32 cols each)
    const int rowBase = blockIdx.y * BMM;
    const int colBase = blockIdx.x * BN;

    float acc[2][4][4];
#pragma unroll
    for (int mi = 0; mi < 2; mi++)
#pragma unroll
        for (int ni = 0; ni < 4; ni++)
#pragma unroll
            for (int r = 0; r < 4; r++) acc[mi][ni][r] = 0.f;

    // ---- stage 0 ----
    {
        int r  = tid >> 2;          // 0..63
        int c4 = tid & 3;
        cp16(&As[0][r][c4 * 4], &A[(size_t)(rowBase + r) * K + c4 * 4]);
    }
#pragma unroll
    for (int i = 0; i < 2; i++) {
        int idx = tid + i * 256;
        int r  = idx >> 5;          // 0..15
        int c4 = idx & 31;
        cp16(&Bs[0][r][c4 * 4], &B[(size_t)r * N + colBase + c4 * 4]);
    }
    CP_COMMIT();
    CP_WAIT0();
    __syncthreads();

    int s = 0;
    for (int k0 = 0; k0 < K; k0 += BKK) {
        const bool nxt = (k0 + BKK) < K;
        if (nxt) {
            {
                int r  = tid >> 2;
                int c4 = tid & 3;
                cp16(&As[s ^ 1][r][c4 * 4],
                     &A[(size_t)(rowBase + r) * K + k0 + BKK + c4 * 4]);
            }
#pragma unroll
            for (int i = 0; i < 2; i++) {
                int idx = tid + i * 256;
                int r  = idx >> 5;
                int c4 = idx & 31;
                cp16(&Bs[s ^ 1][r][c4 * 4],
                     &B[(size_t)(k0 + BKK + r) * N + colBase + c4 * 4]);
            }
            CP_COMMIT();
        }

#pragma unroll
        for (int k8 = 0; k8 < BKK; k8 += 8) {
            uint32_t af[2][4], bf[4][2];
#pragma unroll
            for (int mi = 0; mi < 2; mi++) {
                int row = warpRow + mi * 16 + gid;
                af[mi][0] = __float_as_uint(As[s][row    ][k8 + tig]);
                af[mi][1] = __float_as_uint(As[s][row + 8][k8 + tig]);
                af[mi][2] = __float_as_uint(As[s][row    ][k8 + tig + 4]);
                af[mi][3] = __float_as_uint(As[s][row + 8][k8 + tig + 4]);
            }
#pragma unroll
            for (int ni = 0; ni < 4; ni++) {
                int col = warpCol + ni * 8 + gid;
                bf[ni][0] = __float_as_uint(Bs[s][k8 + tig    ][col]);
                bf[ni][1] = __float_as_uint(Bs[s][k8 + tig + 4][col]);
            }
#pragma unroll
            for (int mi = 0; mi < 2; mi++)
#pragma unroll
                for (int ni = 0; ni < 4; ni++)
                    mma_tf32(acc[mi][ni], af[mi], bf[ni]);
        }

        if (nxt) {
            CP_WAIT0();
            __syncthreads();
            s ^= 1;
        }
    }

#pragma unroll
    for (int mi = 0; mi < 2; mi++) {
        int r0 = rowBase + warpRow + mi * 16 + gid;
#pragma unroll
        for (int ni = 0; ni < 4; ni++) {
            int c = colBase + warpCol + ni * 8 + tig * 2;
            float2 bz = *(const float2*)&bias[c];
            float2 o0, o1;
            o0.x = acc[mi][ni][0] + bz.x;
            o0.y = acc[mi][ni][1] + bz.y;
            o1.x = acc[mi][ni][2] + bz.x;
            o1.y = acc[mi][ni][3] + bz.y;
            *(float2*)&C[(size_t)r0 * N + c]       = o0;
            *(float2*)&C[(size_t)(r0 + 8) * N + c] = o1;
        }
    }
}

// ---------------------------------------------------------------------------
// Tensor-core causal flash attention, v6 (unchanged from R16 — known good).
// ---------------------------------------------------------------------------
#define ABQ 64
#define ABK 64
#define QLD 68
#define KPLD 40        // u32 pairs per K row (32 pairs + 8 pad)
#define VLD 72
#define PLD 68
#define REGA_BYTES (2 * ABK * KPLD * 4)          // 20,480
#define REGB_BYTES (ABK * VLD * 4)               // 18,432

// pair index p (0..31) -> permuted position within row:
// groups of 8: [p0,p4,p1,p5,p2,p6,p3,p7] so (tig, tig+4) pairs sit adjacent.
__device__ __forceinline__ int kpos(int p) {
    return ((p >> 3) << 3) + 2 * (p & 3) + ((p >> 2) & 1);
}

__global__ __launch_bounds__(128)
void attn_tc_kernel(const float* __restrict__ qkv, float* __restrict__ y)
{
    __shared__ __align__(16) unsigned char smraw[REGA_BYTES + REGB_BYTES];
    float*    QKs = (float*)smraw;                 // Q staging [64][68]
    uint32_t* Khi = (uint32_t*)smraw;              // [64][40]
    uint32_t* Klo = Khi + ABK * KPLD;              // [64][40]
    float*    Ps  = (float*)smraw;                 // [64][68] (aliases K region)
    float*    Vs  = (float*)(smraw + REGA_BYTES);  // [64][72]

    const int tid  = threadIdx.x;
    const int warp = tid >> 5;
    const int lane = tid & 31;
    const int gid  = lane >> 2;
    const int tig  = lane & 3;
    const int w16  = warp * 16;
    const int bh   = blockIdx.y;
    const int b    = bh >> 4;
    const int h    = bh & 15;

    const float* base = qkv + (size_t)b * SEQ * QKV_N + h * DHEAD;
    const float* kb   = base + CMODEL;
    const float* vb   = base + 2 * CMODEL;
    float* yb = y + (size_t)b * SEQ * CMODEL + h * DHEAD;
    const float SC = 0.125f;

#pragma unroll 1
    for (int ti = 0; ti < 2; ti++) {
        const int qt = (ti == 0) ? (int)blockIdx.x : 31 - (int)blockIdx.x;
        const int q0 = qt * ABQ;
        const int rowg0 = q0 + w16 + gid;

        // ---- stage Q tile (fp32) into region A ----
#pragma unroll
        for (int i = 0; i < 8; i++) {
            int idx = tid + i * 128;
            int r  = idx >> 4;
            int c4 = idx & 15;
            float4 t = *(const float4*)&base[(size_t)(q0 + r) * QKV_N + c4 * 4];
            *(float4*)&QKs[r * QLD + c4 * 4] = t;
        }
        __syncthreads();

        // ---- build loop-invariant Q bf16 hi/lo A-fragments (split ONCE) ----
        uint32_t qhi[4][4], qlo[4][4];
#pragma unroll
        for (int s16 = 0; s16 < 4; s16++) {
            const int kk = s16 * 16;
            const float* r0p = &QKs[(w16 + gid)     * QLD + kk];
            const float* r8p = &QKs[(w16 + gid + 8) * QLD + kk];
            split_pair_bf16(r0p[2 * tig],     r0p[2 * tig + 1], qhi[s16][0], qlo[s16][0]);
            split_pair_bf16(r8p[2 * tig],     r8p[2 * tig + 1], qhi[s16][1], qlo[s16][1]);
            split_pair_bf16(r0p[2 * tig + 8], r0p[2 * tig + 9], qhi[s16][2], qlo[s16][2]);
            split_pair_bf16(r8p[2 * tig + 8], r8p[2 * tig + 9], qhi[s16][3], qlo[s16][3]);
        }
        __syncthreads();   // Q staging reads done before K loader overwrites

        float yacc[8][4];
#pragma unroll
        for (int nt = 0; nt < 8; nt++)
#pragma unroll
            for (int r = 0; r < 4; r++) yacc[nt][r] = 0.f;

        float mprev[2] = {-CUDART_INF_F, -CUDART_INF_F};
        float lrun[2]  = {0.f, 0.f};

        const int nkt = qt + 1;
#pragma unroll 1
        for (int kt = 0; kt < nkt; kt++) {
            const int k0 = kt * ABK;
            const bool partial = (kt == qt);

            // ---- load K (bf16 hi/lo, pair-permuted) + V (tf32-rounded) ----
#pragma unroll
            for (int i = 0; i < 8; i++) {
                int idx = tid + i * 128;
                int r  = idx >> 4;        // 0..63
                int c4 = idx & 15;
                float4 tk = *(const float4*)&kb[(size_t)(k0 + r) * QKV_N + c4 * 4];
                uint32_t h0, l0, h1, l1;
                split_pair_bf16(tk.x, tk.y, h0, l0);
                split_pair_bf16(tk.z, tk.w, h1, l1);
                int p0 = r * KPLD + kpos(2 * c4);
                int p1 = r * KPLD + kpos(2 * c4 + 1);
                Khi[p0] = h0;  Khi[p1] = h1;
                Klo[p0] = l0;  Klo[p1] = l1;
                float4 tv = *(const float4*)&vb[(size_t)(k0 + r) * QKV_N + c4 * 4];
                float4 rv;
                rv.x = rtf(tv.x); rv.y = rtf(tv.y);
                rv.z = rtf(tv.z); rv.w = rtf(tv.w);
                *(float4*)&Vs[r * VLD + c4 * 4] = rv;
            }
            __syncthreads();

            // ---- S = Q K^T  (3xBF16 m16n8k16) ----
            float sacc[8][4];
#pragma unroll
            for (int ni = 0; ni < 8; ni++)
#pragma unroll
                for (int r = 0; r < 4; r++) sacc[ni][r] = 0.f;

#pragma unroll
            for (int s16 = 0; s16 < 4; s16++) {
#pragma unroll
                for (int ni = 0; ni < 8; ni++) {
                    const int col = ni * 8 + gid;
                    const int off = col * KPLD + 8 * s16 + 2 * tig;
                    uint2 bhp = *(const uint2*)&Khi[off];
                    uint2 blp = *(const uint2*)&Klo[off];
                    mma_bf16(sacc[ni], qhi[s16], blp.x, blp.y);
                    mma_bf16(sacc[ni], qlo[s16], bhp.x, bhp.y);
                    mma_bf16(sacc[ni], qhi[s16], bhp.x, bhp.y);
                }
            }
            __syncthreads();   // K fully dead before Ps overwrites region A

            // ---- online softmax; write P (tf32-rounded) to Ps ----
            float alpha[2];
#pragma unroll
            for (int hf = 0; hf < 2; hf++) {
                const int rowg = rowg0 + 8 * hf;
                float mt = -CUDART_INF_F;
#pragma unroll
                for (int ni = 0; ni < 8; ni++) {
#pragma unroll
                    for (int c = 0; c < 2; c++) {
                        float v = sacc[ni][2 * hf + c] * SC;
                        if (partial) {
                            int key = k0 + ni * 8 + 2 * tig + c;
                            if (key > rowg) v = -CUDART_INF_F;
                        }
                        sacc[ni][2 * hf + c] = v;
                        mt = fmaxf(mt, v);
                    }
                }
                mt = fmaxf(mt, __shfl_xor_sync(0xffffffffu, mt, 1));
                mt = fmaxf(mt, __shfl_xor_sync(0xffffffffu, mt, 2));
                float mn = fmaxf(mprev[hf], mt);
                float al2 = __expf(mprev[hf] - mn);
                float lsum = 0.f;
#pragma unroll
                for (int ni = 0; ni < 8; ni++) {
                    float p0 = __expf(sacc[ni][2 * hf + 0] - mn);
                    float p1 = __expf(sacc[ni][2 * hf + 1] - mn);
                    lsum += p0 + p1;
                    *(float2*)&Ps[(w16 + gid + 8 * hf) * PLD + ni * 8 + 2 * tig] =
                        make_float2(rtf(p0), rtf(p1));
                }
                lsum += __shfl_xor_sync(0xffffffffu, lsum, 1);
                lsum += __shfl_xor_sync(0xffffffffu, lsum, 2);
                lrun[hf] = al2 * lrun[hf] + lsum;
                mprev[hf] = mn;
                alpha[hf] = al2;
            }
#pragma unroll
            for (int nt = 0; nt < 8; nt++) {
                yacc[nt][0] *= alpha[0];
                yacc[nt][1] *= alpha[0];
                yacc[nt][2] *= alpha[1];
                yacc[nt][3] *= alpha[1];
            }
            __syncwarp();   // own-warp P rows visible to own fragment loads

            // ---- O += P V  (single tf32 m16n8k8; 64-deep K) ----
#pragma unroll
            for (int s8 = 0; s8 < 8; s8++) {
                const int kk = s8 * 8;
                uint32_t af[4];
                af[0] = __float_as_uint(Ps[(w16 + gid)     * PLD + kk + tig]);
                af[1] = __float_as_uint(Ps[(w16 + gid + 8) * PLD + kk + tig]);
                af[2] = __float_as_uint(Ps[(w16 + gid)     * PLD + kk + tig + 4]);
                af[3] = __float_as_uint(Ps[(w16 + gid + 8) * PLD + kk + tig + 4]);
#pragma unroll
                for (int nt = 0; nt < 8; nt++) {
                    uint32_t bv[2];
                    bv[0] = __float_as_uint(Vs[(kk + tig)     * VLD + nt * 8 + gid]);
                    bv[1] = __float_as_uint(Vs[(kk + tig + 4) * VLD + nt * 8 + gid]);
                    mma_tf32(yacc[nt], af, bv);
                }
            }
            __syncthreads();   // P/V readers done before next loaders overwrite
        }

        // ---- epilogue for this tile: divide by l, round to tf32, store ----
        float linv0 = 1.f / lrun[0];
        float linv1 = 1.f / lrun[1];
#pragma unroll
        for (int nt = 0; nt < 8; nt++) {
            int c = nt * 8 + 2 * tig;
            float2 o0, o1;
            o0.x = rtf(yacc[nt][0] * linv0);
            o0.y = rtf(yacc[nt][1] * linv0);
            o1.x = rtf(yacc[nt][2] * linv1);
            o1.y = rtf(yacc[nt][3] * linv1);
            *(float2*)&yb[(size_t)(rowg0)     * CMODEL + c] = o0;
            *(float2*)&yb[(size_t)(rowg0 + 8) * CMODEL + c] = o1;
        }
    }
}

// ---------------------------------------------------------------------------
// Launch
// ---------------------------------------------------------------------------
extern "C" void kernel_launch(void* const* d_in, const int* in_sizes, int n_in,
                              void* d_out, int out_size)
{
    const float* x     = (const float*)d_in[0];
    const float* w_qkv = (const float*)d_in[1];
    const float* b_qkv = (const float*)d_in[2];
    const float* w_out = (const float*)d_in[3];
    const float* b_out = (const float*)d_in[4];

    float *qkv, *yy, *xc, *wqc, *woc;
    cudaGetSymbolAddress((void**)&qkv, g_qkv);
    cudaGetSymbolAddress((void**)&yy,  g_y);
    cudaGetSymbolAddress((void**)&xc,  g_xc);
    cudaGetSymbolAddress((void**)&wqc, g_wqkvc);
    cudaGetSymbolAddress((void**)&woc, g_woutc);

    float* out = (float*)d_out;

    // 0) pre-round operands to tf32 (numerically identical to cvt-at-load)
    {
        int n4x = MROWS * CMODEL / 4;
        cvt_tf32_kernel<<<n4x / 256, 256>>>(x, xc, n4x);
        int n4q = CMODEL * QKV_N / 4;
        cvt_tf32_kernel<<<n4q / 256, 256>>>(w_qkv, wqc, n4q);
        int n4o = CMODEL * CMODEL / 4;
        cvt_tf32_kernel<<<n4o / 256, 256>>>(w_out, woc, n4o);
    }
    // 1) QKV projection
    {
        dim3 grid(QKV_N / BN, MROWS / BMM);  // (24, 64)
        tf32_gemm_bias<<<grid, 256>>>(xc, wqc, b_qkv, qkv,
                                      MROWS, QKV_N, CMODEL);
    }
    // 2) causal flash attention (paired q-tiles: bx and 31-bx)
    {
        dim3 grid(16, BATCH * NHEADS);       // (16, 32), 512 uniform CTAs
        attn_tc_kernel<<<grid, 128>>>(qkv, yy);
    }
    // 3) output projection
    {
        dim3 grid(CMODEL / BN, MROWS / BMM); // (8, 64)
        tf32_gemm_bias<<<grid, 256>>>(yy, woc, b_out, out,
                                      MROWS, CMODEL, CMODEL);
    }
}